// round 12
// baseline (speedup 1.0000x reference)
#include <cuda_runtime.h>
#include <cuda_bf16.h>
#include <cstdint>
#include <cstring>

// NanEuclidean: X[4096,1024] f32, Y[4096,1024] f32 (10% NaN) -> out[4096,4096] f32
//
// R12: missing-mask reformulation.
//   d  = rowsumXX + colsumYY - 2*Xc.Yc^T - XX.mY^T - mX.YY^T
//   pc = 1024 - nmX - nmY + mX.mY^T
// Xc.Yc in bf16 (m16n8k16); XX.mY, mX.YY, mX.mY in e4m3 (m16n8k32; masks exact).
// Per-(rb,kb) 16KB blocks: [bf16 tile 8K][fp8 plane1 4K][fp8 plane2 4K], swizzled.

#define NKB    32
#define BLK16K 16384u
#define STAGEB 32768u        // A block 16K + B block 16K
#define NSTAGE 4
#define GSMEM  (NSTAGE * STAGEB + 1024u)

// 16 MB each: [row_block(32)][k_block(32)] 16KB blocks
__device__ __align__(1024) char g_A[16777216];   // [Xc bf16][-XX e4m3][mX e4m3]
__device__ __align__(1024) char g_B[16777216];   // [-2Yc bf16][mY e4m3][-YY e4m3]
// reductions: [0:4096)=rowsumXX [4096:8192)=nmX [8192:12288)=colsumYY [12288:16384)=nmY
__device__ float g_red[16384];

// ---------------- helpers ----------------
__device__ __forceinline__ uint32_t bf2_u32(__nv_bfloat162 v) {
    uint32_t u; memcpy(&u, &v, 4); return u;
}
__device__ __forceinline__ uint32_t smem_u32(const void* p) {
    uint32_t a;
    asm("{ .reg .u64 t; cvta.to.shared.u64 t, %1; cvt.u32.u64 %0, t; }" : "=r"(a) : "l"(p));
    return a;
}
__device__ __forceinline__ void cpasync16(uint32_t dst, const void* src) {
    asm volatile("cp.async.cg.shared.global [%0], [%1], 16;" :: "r"(dst), "l"(src) : "memory");
}
#define LDSM4(r0, r1, r2, r3, addr) \
    asm volatile("ldmatrix.sync.aligned.m8n8.x4.shared.b16 {%0,%1,%2,%3}, [%4];" \
        : "=r"(r0), "=r"(r1), "=r"(r2), "=r"(r3) : "r"(addr))

__device__ __forceinline__ void mma16816(float* c, const uint32_t* a, const uint32_t* b) {
    asm volatile(
        "mma.sync.aligned.m16n8k16.row.col.f32.bf16.bf16.f32 "
        "{%0,%1,%2,%3}, {%4,%5,%6,%7}, {%8,%9}, {%0,%1,%2,%3};"
        : "+f"(c[0]), "+f"(c[1]), "+f"(c[2]), "+f"(c[3])
        : "r"(a[0]), "r"(a[1]), "r"(a[2]), "r"(a[3]), "r"(b[0]), "r"(b[1]));
}
__device__ __forceinline__ void mma16832(float* c, const uint32_t* a, const uint32_t* b) {
    asm volatile(
        "mma.sync.aligned.m16n8k32.row.col.f32.e4m3.e4m3.f32 "
        "{%0,%1,%2,%3}, {%4,%5,%6,%7}, {%8,%9}, {%0,%1,%2,%3};"
        : "+f"(c[0]), "+f"(c[1]), "+f"(c[2]), "+f"(c[3])
        : "r"(a[0]), "r"(a[1]), "r"(a[2]), "r"(a[3]), "r"(b[0]), "r"(b[1]));
}
__device__ __forceinline__ uint16_t f2e4m3x2(float hi, float lo) {
    uint16_t h;
    asm("cvt.rn.satfinite.e4m3x2.f32 %0, %1, %2;" : "=h"(h) : "f"(hi), "f"(lo));
    return h;
}
__device__ __forceinline__ bool nan_bits(float x) {
    return (__float_as_uint(x) & 0x7fffffffu) > 0x7f800000u;  // fast-math safe
}

// ---------------- Kernel 0: zero the reduction buffers ----------------
__global__ void nanEuc_zero() {
    unsigned i = blockIdx.x * 256u + threadIdx.x;
    if (i < 16384u) g_red[i] = 0.f;
}

// ---------------- Kernel 1: component planes + rowsum/count reductions ----------------
__global__ void __launch_bounds__(256) nanEuc_prep(const float* __restrict__ X,
                                                   const float* __restrict__ Y) {
    const int is_b   = (int)(blockIdx.x >> 11);      // 2048 blocks per matrix
    const float* src = is_b ? Y : X;
    unsigned idx = (blockIdx.x & 2047u) * 256u + threadIdx.x;
    unsigned s   = idx & 3u;              // 8-elem segment within 32-k block
    unsigned kb  = (idx >> 2) & 31u;      // k block of 32
    unsigned row = idx >> 7;              // 0..4095  (constant across a warp)

    const float4 v0 = *reinterpret_cast<const float4*>(src + (size_t)row * 1024u + kb * 32u + s * 8u);
    const float4 v1 = *reinterpret_cast<const float4*>(src + (size_t)row * 1024u + kb * 32u + s * 8u + 4u);
    float x[8] = {v0.x, v0.y, v0.z, v0.w, v1.x, v1.y, v1.z, v1.w};

    float sxx = 0.f, cnt = 0.f;
    uint32_t bfp[4]; uint16_t sq[4], mk[4];
    #pragma unroll
    for (int i = 0; i < 4; i++) {
        float e0 = x[2 * i], e1 = x[2 * i + 1];
        bool  m0 = nan_bits(e0), m1 = nan_bits(e1);
        float a0 = m0 ? 0.f : e0, a1 = m1 ? 0.f : e1;
        float q0 = a0 * a0, q1 = a1 * a1;
        sxx += q0 + q1;
        cnt += (m0 ? 1.f : 0.f) + (m1 ? 1.f : 0.f);
        float f0 = is_b ? -2.f * a0 : a0;
        float f1 = is_b ? -2.f * a1 : a1;
        bfp[i] = bf2_u32(__floats2bfloat162_rn(f0, f1));
        sq[i]  = f2e4m3x2(-q1, -q0);                                  // bytes: [-q0][-q1]
        mk[i]  = (uint16_t)((m0 ? 0x38u : 0u) | ((m1 ? 0x38u : 0u) << 8));  // e4m3 1.0
    }

    char* blk = (is_b ? g_B : g_A) + ((size_t)(row >> 7) * 32u + kb) * BLK16K;
    unsigned r = row & 127u;
    // bf16 tile: 128 rows x 64B, seg swizzle s ^ ((r>>1)&3)
    unsigned offb = r * 64u + ((s ^ ((r >> 1) & 3u)) << 4);
    *reinterpret_cast<uint4*>(blk + offb) = make_uint4(bfp[0], bfp[1], bfp[2], bfp[3]);
    // fp8 tiles: 128 rows x 32B, seg swizzle s8 ^ ((r>>2)&1)
    unsigned off8 = r * 32u + ((((s >> 1) ^ ((r >> 2) & 1u))) << 4) + (s & 1u) * 8u;
    uint2 sqv = make_uint2((uint32_t)sq[0] | ((uint32_t)sq[1] << 16),
                           (uint32_t)sq[2] | ((uint32_t)sq[3] << 16));
    uint2 mkv = make_uint2((uint32_t)mk[0] | ((uint32_t)mk[1] << 16),
                           (uint32_t)mk[2] | ((uint32_t)mk[3] << 16));
    *reinterpret_cast<uint2*>(blk +  8192u + off8) = is_b ? mkv : sqv;  // A:-XX  B:mY
    *reinterpret_cast<uint2*>(blk + 12288u + off8) = is_b ? sqv : mkv;  // A:mX   B:-YY

    // warp reduction (whole warp shares one row)
    #pragma unroll
    for (int o = 16; o; o >>= 1) {
        sxx += __shfl_xor_sync(0xffffffffu, sxx, o);
        cnt += __shfl_xor_sync(0xffffffffu, cnt, o);
    }
    if ((threadIdx.x & 31) == 0) {
        atomicAdd(&g_red[(is_b ? 8192 : 0) + row], sxx);
        atomicAdd(&g_red[(is_b ? 12288 : 4096) + row], cnt);
    }
}

// ---------------- Kernel 2: mixed bf16/fp8 GEMM ----------------
// 512 threads = 16 warps in 4x4; warp tile 32x32; CTA tile 128x128.
__global__ void __launch_bounds__(512, 1) nanEuc_gemm(float* __restrict__ out) {
    extern __shared__ char smraw[];
    const uint32_t smbase = (smem_u32(smraw) + 1023u) & ~1023u;

    const int tid = threadIdx.x, lane = tid & 31, w = tid >> 5;
    const int wr = w >> 2, wc = w & 3;
    const int cb = blockIdx.x, rb = blockIdx.y;

    float accD[2][4][4];
    float accP[2][4][4];
    #pragma unroll
    for (int mi = 0; mi < 2; mi++)
        #pragma unroll
        for (int ni = 0; ni < 4; ni++)
            #pragma unroll
            for (int q = 0; q < 4; q++) { accD[mi][ni][q] = 0.f; accP[mi][ni][q] = 0.f; }

    // bf16 ldmatrix addressing (64B rows, seg swizzle s^((row>>1)&3))
    const uint32_t hiA = (uint32_t)(lane >> 4);
    const uint32_t hiB = (uint32_t)((lane >> 3) & 1);
    uint32_t rtermA[2], xorA[2], rtermB[2], xorB[2];
    #pragma unroll
    for (int mi = 0; mi < 2; mi++) {
        uint32_t rowA = wr * 32 + mi * 16 + (lane & 15);
        rtermA[mi] = rowA * 64u;  xorA[mi] = (rowA >> 1) & 3u;
    }
    #pragma unroll
    for (int nt = 0; nt < 2; nt++) {
        uint32_t rowB = wc * 32 + nt * 16 + (lane & 7) + ((lane >> 4) & 1) * 8;
        rtermB[nt] = rowB * 64u;  xorB[nt] = (rowB >> 1) & 3u;
    }
    // fp8 ldmatrix addressing (32B rows, seg swizzle s^((row>>2)&1))
    uint32_t addrA8[2], addrB8[2];
    #pragma unroll
    for (int mi = 0; mi < 2; mi++) {
        uint32_t rw = wr * 32 + mi * 16 + (lane & 7) + ((lane >> 3) & 1) * 8;
        uint32_t sg = (uint32_t)(lane >> 4) & 1u;
        addrA8[mi] = rw * 32u + ((sg ^ ((rw >> 2) & 1u)) << 4);
    }
    #pragma unroll
    for (int nt = 0; nt < 2; nt++) {
        uint32_t rw = wc * 32 + nt * 16 + (lane & 7) + ((lane >> 4) & 1) * 8;
        uint32_t sg = (uint32_t)(lane >> 3) & 1u;
        addrB8[nt] = rw * 32u + ((sg ^ ((rw >> 2) & 1u)) << 4);
    }

    // stage loader: A block 16KB + B block 16KB, contiguous 16B cp.async
    auto load_stage = [&](int slot, int c) {
        const uint32_t dst0 = smbase + (uint32_t)slot * STAGEB;
        const char* Ab = g_A + ((size_t)rb * 32u + c) * BLK16K;
        const char* Bb = g_B + ((size_t)cb * 32u + c) * BLK16K;
        #pragma unroll
        for (int i = tid; i < 2048; i += 512) {
            const char* src = (i < 1024) ? Ab + (size_t)i * 16u : Bb + (size_t)(i - 1024) * 16u;
            cpasync16(dst0 + (uint32_t)i * 16u, src);
        }
    };

    #pragma unroll
    for (int c = 0; c < NSTAGE - 1; c++) {
        load_stage(c, c);
        asm volatile("cp.async.commit_group;" ::: "memory");
    }

    for (int c = 0; c < NKB; c++) {
        asm volatile("cp.async.wait_group %0;" :: "n"(NSTAGE - 2) : "memory");
        __syncthreads();
        if (c + NSTAGE - 1 < NKB) load_stage((c + NSTAGE - 1) & (NSTAGE - 1), c + NSTAGE - 1);
        asm volatile("cp.async.commit_group;" ::: "memory");

        const uint32_t base = smbase + (uint32_t)(c & (NSTAGE - 1)) * STAGEB;

        // ---- bf16: accD += Xc . (-2Yc)^T ----
        #pragma unroll
        for (int kk = 0; kk < 2; kk++) {
            const uint32_t sA = (uint32_t)kk * 2u + hiA;
            const uint32_t sB = (uint32_t)kk * 2u + hiB;
            uint32_t a[2][4], b[4][2];
            #pragma unroll
            for (int mi = 0; mi < 2; mi++)
                LDSM4(a[mi][0], a[mi][1], a[mi][2], a[mi][3],
                      base + rtermA[mi] + ((sA ^ xorA[mi]) << 4));
            #pragma unroll
            for (int nt = 0; nt < 2; nt++)
                LDSM4(b[2 * nt][0], b[2 * nt][1], b[2 * nt + 1][0], b[2 * nt + 1][1],
                      base + 16384u + rtermB[nt] + ((sB ^ xorB[nt]) << 4));
            #pragma unroll
            for (int mi = 0; mi < 2; mi++)
                #pragma unroll
                for (int ni = 0; ni < 4; ni++) mma16816(accD[mi][ni], a[mi], b[ni]);
        }

        // ---- fp8: accD += (-XX).mY^T + mX.(-YY)^T ; accP += mX.mY^T ----
        uint32_t fmY[4][2], fmX[2][4];
        #pragma unroll
        for (int nt = 0; nt < 2; nt++)
            LDSM4(fmY[2 * nt][0], fmY[2 * nt][1], fmY[2 * nt + 1][0], fmY[2 * nt + 1][1],
                  base + 24576u + addrB8[nt]);
        {
            uint32_t fA[2][4];
            #pragma unroll
            for (int mi = 0; mi < 2; mi++)
                LDSM4(fA[mi][0], fA[mi][1], fA[mi][2], fA[mi][3], base + 8192u + addrA8[mi]);
            #pragma unroll
            for (int mi = 0; mi < 2; mi++)
                #pragma unroll
                for (int ni = 0; ni < 4; ni++) mma16832(accD[mi][ni], fA[mi], fmY[ni]);
        }
        #pragma unroll
        for (int mi = 0; mi < 2; mi++)
            LDSM4(fmX[mi][0], fmX[mi][1], fmX[mi][2], fmX[mi][3], base + 12288u + addrA8[mi]);
        {
            uint32_t fB[4][2];
            #pragma unroll
            for (int nt = 0; nt < 2; nt++)
                LDSM4(fB[2 * nt][0], fB[2 * nt][1], fB[2 * nt + 1][0], fB[2 * nt + 1][1],
                      base + 28672u + addrB8[nt]);
            #pragma unroll
            for (int mi = 0; mi < 2; mi++)
                #pragma unroll
                for (int ni = 0; ni < 4; ni++) mma16832(accD[mi][ni], fmX[mi], fB[ni]);
        }
        #pragma unroll
        for (int mi = 0; mi < 2; mi++)
            #pragma unroll
            for (int ni = 0; ni < 4; ni++) mma16832(accP[mi][ni], fmX[mi], fmY[ni]);
    }

    // ---- epilogue ----
    const int r0 = rb * 128 + wr * 32 + (lane >> 2);
    const int c0 = cb * 128 + wc * 32 + (lane & 3) * 2;
    #pragma unroll
    for (int mi = 0; mi < 2; mi++) {
        const int rr = r0 + mi * 16;
        const float rs0 = __ldg(&g_red[rr]),        rs1 = __ldg(&g_red[rr + 8]);
        const float rc0 = __ldg(&g_red[4096 + rr]), rc1 = __ldg(&g_red[4096 + rr + 8]);
        #pragma unroll
        for (int ni = 0; ni < 4; ni++) {
            const int cc = c0 + ni * 8;
            const float cs0 = __ldg(&g_red[8192 + cc]),  cs1 = __ldg(&g_red[8192 + cc + 1]);
            const float cn0 = __ldg(&g_red[12288 + cc]), cn1 = __ldg(&g_red[12288 + cc + 1]);
            float v[4];
            #pragma unroll
            for (int q = 0; q < 4; q++) {
                const float rs = (q >> 1) ? rs1 : rs0, rc = (q >> 1) ? rc1 : rc0;
                const float cs = (q & 1) ? cs1 : cs0,  cn = (q & 1) ? cn1 : cn0;
                float d  = rs + cs + accD[mi][ni][q];
                float pc = 1024.f - rc - cn + accP[mi][ni][q];
                v[q] = (pc == 0.f) ? __int_as_float(0x7fc00000)
                                   : sqrtf(fmaxf(d, 0.f) * 1024.f / fmaxf(pc, 1.f));
            }
            *reinterpret_cast<float2*>(out + (size_t)rr * 4096u + cc)       = make_float2(v[0], v[1]);
            *reinterpret_cast<float2*>(out + (size_t)(rr + 8) * 4096u + cc) = make_float2(v[2], v[3]);
        }
    }
}

// ---------------- launch ----------------
extern "C" void kernel_launch(void* const* d_in, const int* in_sizes, int n_in,
                              void* d_out, int out_size) {
    (void)in_sizes; (void)n_in; (void)out_size;
    const float* X = (const float*)d_in[0];
    const float* Y = (const float*)d_in[1];
    float* out = (float*)d_out;

    nanEuc_zero<<<64, 256>>>();
    nanEuc_prep<<<4096, 256>>>(X, Y);

    cudaFuncSetAttribute(nanEuc_gemm, cudaFuncAttributeMaxDynamicSharedMemorySize, GSMEM);
    nanEuc_gemm<<<dim3(32, 32, 1), 512, GSMEM>>>(out);
}

// round 13
// speedup vs baseline: 1.1964x; 1.1964x over previous
#include <cuda_runtime.h>
#include <cuda_bf16.h>
#include <cstdint>
#include <cstring>

// NanEuclidean: X[4096,1024] f32, Y[4096,1024] f32 (10% NaN) -> out[4096,4096] f32
//   d = sqrt( clip(XX.pY - 2 Xc.Yc + pX.YY, 0) / max(1, pX.pY) * 1024 ), NaN where pc==0
//
// R13 = R11 compute (bf16 mma.sync, dual f32 accumulators, 4-stage K32 pipeline)
//       + persistent CTAs with a flat cross-tile pipeline (no drain between tiles)
//       + memset-based reduction zeroing.

#define NKB    32            // K chunks of 32 per tile
#define TILE8K 8192u         // one 128-row x 64-byte swizzled tile image
#define STAGEB (6u * TILE8K) // A0 A1 A2 B0 B1 B2 = 48 KB
#define NSTAGE 4
#define GSMEM  (NSTAGE * STAGEB + 1024u)
#define NSM    148
#define NTILES 1024

// 24 MB each: [row_block(32)][comp(3)][k_block(32)] 8KB tiles
__device__ __align__(1024) __nv_bfloat16 g_nanEuc_A[12582912ull];
__device__ __align__(1024) __nv_bfloat16 g_nanEuc_B[12582912ull];

// ---------------- helpers ----------------
__device__ __forceinline__ uint32_t bf2_u32(__nv_bfloat162 v) {
    uint32_t u; memcpy(&u, &v, 4); return u;
}
__device__ __forceinline__ uint32_t smem_u32(const void* p) {
    uint32_t a;
    asm("{ .reg .u64 t; cvta.to.shared.u64 t, %1; cvt.u32.u64 %0, t; }" : "=r"(a) : "l"(p));
    return a;
}
__device__ __forceinline__ void cpasync16(uint32_t dst, const void* src) {
    asm volatile("cp.async.cg.shared.global [%0], [%1], 16;" :: "r"(dst), "l"(src) : "memory");
}
#define LDSM4(r0, r1, r2, r3, addr) \
    asm volatile("ldmatrix.sync.aligned.m8n8.x4.shared.b16 {%0,%1,%2,%3}, [%4];" \
        : "=r"(r0), "=r"(r1), "=r"(r2), "=r"(r3) : "r"(addr))

__device__ __forceinline__ void mma16816(float* c, const uint32_t* a, const uint32_t* b) {
    asm volatile(
        "mma.sync.aligned.m16n8k16.row.col.f32.bf16.bf16.f32 "
        "{%0,%1,%2,%3}, {%4,%5,%6,%7}, {%8,%9}, {%0,%1,%2,%3};"
        : "+f"(c[0]), "+f"(c[1]), "+f"(c[2]), "+f"(c[3])
        : "r"(a[0]), "r"(a[1]), "r"(a[2]), "r"(a[3]), "r"(b[0]), "r"(b[1]));
}
__device__ __forceinline__ bool nan_bits(float x) {
    return (__float_as_uint(x) & 0x7fffffffu) > 0x7f800000u;  // fast-math safe
}

// ---------------- Kernel 1: precompute swizzled bf16 component tiles ----------------
// A comps (from X): [XX, Xc, pX].  B comps (from Y): [pY, -2*Yc, YY].
// Tile: 128 rows x 64B (32 bf16). 16B seg s stored at local seg s ^ ((r>>1)&3).
__global__ void __launch_bounds__(256) nanEuc_prep(const float* __restrict__ X,
                                                   const float* __restrict__ Y) {
    const int is_b   = (int)(blockIdx.x >> 11);       // 2048 blocks per matrix
    const float* src = is_b ? Y : X;
    unsigned idx = (blockIdx.x & 2047u) * 256u + threadIdx.x;  // 0..524287
    unsigned s   = idx & 3u;              // 16B seg within 64B (8 bf16 = 8 f32 in)
    unsigned kb  = (idx >> 2) & 31u;      // k block of 32
    unsigned row = idx >> 7;              // 0..4095

    const float4 v0 = *reinterpret_cast<const float4*>(src + (size_t)row * 1024u + kb * 32u + s * 8u);
    const float4 v1 = *reinterpret_cast<const float4*>(src + (size_t)row * 1024u + kb * 32u + s * 8u + 4u);
    float x[8] = {v0.x, v0.y, v0.z, v0.w, v1.x, v1.y, v1.z, v1.w};

    uint32_t c0[4], c1[4], c2[4];         // 4 bf16x2 per comp
    #pragma unroll
    for (int i = 0; i < 4; i++) {
        float e0 = x[2 * i], e1 = x[2 * i + 1];
        bool  m0 = nan_bits(e0), m1 = nan_bits(e1);
        float a0 = m0 ? 0.f : e0, a1 = m1 ? 0.f : e1;
        float p0 = m0 ? 0.f : 1.f, p1 = m1 ? 0.f : 1.f;
        float q0 = a0 * a0, q1 = a1 * a1;
        if (!is_b) {
            c0[i] = bf2_u32(__floats2bfloat162_rn(q0, q1));                 // XX
            c1[i] = bf2_u32(__floats2bfloat162_rn(a0, a1));                 // Xc
            c2[i] = bf2_u32(__floats2bfloat162_rn(p0, p1));                 // pX
        } else {
            c0[i] = bf2_u32(__floats2bfloat162_rn(p0, p1));                 // pY
            c1[i] = bf2_u32(__floats2bfloat162_rn(-2.f * a0, -2.f * a1));   // -2Yc
            c2[i] = bf2_u32(__floats2bfloat162_rn(q0, q1));                 // YY
        }
    }

    unsigned rb = row >> 7, r = row & 127u;
    unsigned off = r * 64u + ((s ^ ((r >> 1) & 3u)) << 4);   // swizzled 16B slot
    char* dst = reinterpret_cast<char*>(is_b ? g_nanEuc_B : g_nanEuc_A);
    size_t tb = ((size_t)rb * 96u + kb) * 8192u;             // [rb][comp][kb]; comp stride 32*8192
    *reinterpret_cast<uint4*>(dst + tb +           off) = make_uint4(c0[0], c0[1], c0[2], c0[3]);
    *reinterpret_cast<uint4*>(dst + tb + 262144u + off) = make_uint4(c1[0], c1[1], c1[2], c1[3]);
    *reinterpret_cast<uint4*>(dst + tb + 524288u + off) = make_uint4(c2[0], c2[1], c2[2], c2[3]);
}

// ---------------- Kernel 2: persistent mma.sync GEMM, flat cross-tile pipeline ----------------
// 512 threads = 16 warps in 4x4; warp tile 32x32; CTA tile 128x128.
__global__ void __launch_bounds__(512, 1) nanEuc_gemm(float* __restrict__ out) {
    extern __shared__ char smraw[];
    const uint32_t smbase = (smem_u32(smraw) + 1023u) & ~1023u;

    const int tid = threadIdx.x, lane = tid & 31, w = tid >> 5;
    const int wr = w >> 2, wc = w & 3;
    const int bid = blockIdx.x;

    const char* Ag = reinterpret_cast<const char*>(g_nanEuc_A);
    const char* Bg = reinterpret_cast<const char*>(g_nanEuc_B);

    float accD[2][4][4];
    float accP[2][4][4];
    #pragma unroll
    for (int mi = 0; mi < 2; mi++)
        #pragma unroll
        for (int ni = 0; ni < 4; ni++)
            #pragma unroll
            for (int q = 0; q < 4; q++) { accD[mi][ni][q] = 0.f; accP[mi][ni][q] = 0.f; }

    // ldmatrix lane addressing (64B rows, seg swizzle s^((row>>1)&3))
    const uint32_t hiA = (uint32_t)(lane >> 4);
    const uint32_t hiB = (uint32_t)((lane >> 3) & 1);
    uint32_t rtermA[2], xorA[2], rtermB[2], xorB[2];
    #pragma unroll
    for (int mi = 0; mi < 2; mi++) {
        uint32_t rowA = wr * 32 + mi * 16 + (lane & 15);
        rtermA[mi] = rowA * 64u;  xorA[mi] = (rowA >> 1) & 3u;
    }
    #pragma unroll
    for (int nt = 0; nt < 2; nt++) {
        uint32_t rowB = wc * 32 + nt * 16 + (lane & 7) + ((lane >> 4) & 1) * 8;
        rtermB[nt] = rowB * 64u;  xorB[nt] = (rowB >> 1) & 3u;
    }

    const int myNT  = (NTILES - bid + NSM - 1) / NSM;   // tiles handled by this CTA
    const int total = myNT * NKB;                        // flat chunk count

    // flat-chunk stage loader: g -> (tile, chunk); 6 contiguous 8KB tiles
    auto load_stage = [&](int slot, int g) {
        const int t  = bid + (g >> 5) * NSM;
        const int c  = g & 31;
        const int rb = t >> 5, cb = t & 31;
        const uint32_t dst0 = smbase + (uint32_t)slot * STAGEB;
        #pragma unroll
        for (int i = tid; i < (int)(STAGEB / 16u); i += 512) {
            int tt = i >> 9;                  // 0..5
            int comp = (tt < 3) ? tt : tt - 3;
            const char* src = (tt < 3
                ? Ag + ((size_t)(rb * 3 + comp) * NKB + c) * TILE8K
                : Bg + ((size_t)(cb * 3 + comp) * NKB + c) * TILE8K)
                + (size_t)(i & 511) * 16u;
            cpasync16(dst0 + (uint32_t)i * 16u, src);
        }
    };

    // prologue: 3 stages in flight
    #pragma unroll
    for (int g = 0; g < NSTAGE - 1; g++) {
        load_stage(g, g);
        asm volatile("cp.async.commit_group;" ::: "memory");
    }

    for (int g = 0; g < total; g++) {
        asm volatile("cp.async.wait_group %0;" :: "n"(NSTAGE - 2) : "memory");
        __syncthreads();
        if (g + NSTAGE - 1 < total) load_stage((g + NSTAGE - 1) & (NSTAGE - 1), g + NSTAGE - 1);
        asm volatile("cp.async.commit_group;" ::: "memory");   // empty group keeps count

        const uint32_t base = smbase + (uint32_t)(g & (NSTAGE - 1)) * STAGEB;
        #pragma unroll
        for (int kk = 0; kk < 2; kk++) {
            const uint32_t sA = (uint32_t)kk * 2u + hiA;
            const uint32_t sB = (uint32_t)kk * 2u + hiB;
            uint32_t a[2][4], b[4][2], bP[4][2];

            // ---- comp 0: D += XX . pY^T ; save pY frags for PC ----
            #pragma unroll
            for (int mi = 0; mi < 2; mi++)
                LDSM4(a[mi][0], a[mi][1], a[mi][2], a[mi][3],
                      base + 0u * TILE8K + rtermA[mi] + ((sA ^ xorA[mi]) << 4));
            #pragma unroll
            for (int nt = 0; nt < 2; nt++)
                LDSM4(b[2 * nt][0], b[2 * nt][1], b[2 * nt + 1][0], b[2 * nt + 1][1],
                      base + 3u * TILE8K + rtermB[nt] + ((sB ^ xorB[nt]) << 4));
            #pragma unroll
            for (int ni = 0; ni < 4; ni++) { bP[ni][0] = b[ni][0]; bP[ni][1] = b[ni][1]; }
            #pragma unroll
            for (int mi = 0; mi < 2; mi++)
                #pragma unroll
                for (int ni = 0; ni < 4; ni++) mma16816(accD[mi][ni], a[mi], b[ni]);

            // ---- comp 1: D += Xc . (-2 Yc)^T ----
            #pragma unroll
            for (int mi = 0; mi < 2; mi++)
                LDSM4(a[mi][0], a[mi][1], a[mi][2], a[mi][3],
                      base + 1u * TILE8K + rtermA[mi] + ((sA ^ xorA[mi]) << 4));
            #pragma unroll
            for (int nt = 0; nt < 2; nt++)
                LDSM4(b[2 * nt][0], b[2 * nt][1], b[2 * nt + 1][0], b[2 * nt + 1][1],
                      base + 4u * TILE8K + rtermB[nt] + ((sB ^ xorB[nt]) << 4));
            #pragma unroll
            for (int mi = 0; mi < 2; mi++)
                #pragma unroll
                for (int ni = 0; ni < 4; ni++) mma16816(accD[mi][ni], a[mi], b[ni]);

            // ---- comp 2: D += pX . YY^T ; PC += pX . pY^T (reuses bP) ----
            #pragma unroll
            for (int mi = 0; mi < 2; mi++)
                LDSM4(a[mi][0], a[mi][1], a[mi][2], a[mi][3],
                      base + 2u * TILE8K + rtermA[mi] + ((sA ^ xorA[mi]) << 4));
            #pragma unroll
            for (int nt = 0; nt < 2; nt++)
                LDSM4(b[2 * nt][0], b[2 * nt][1], b[2 * nt + 1][0], b[2 * nt + 1][1],
                      base + 5u * TILE8K + rtermB[nt] + ((sB ^ xorB[nt]) << 4));
            #pragma unroll
            for (int mi = 0; mi < 2; mi++)
                #pragma unroll
                for (int ni = 0; ni < 4; ni++) {
                    mma16816(accD[mi][ni], a[mi], b[ni]);
                    mma16816(accP[mi][ni], a[mi], bP[ni]);
                }
        }

        // ---- per-tile epilogue + accumulator reset (pipeline keeps flowing) ----
        if ((g & 31) == 31) {
            const int t  = bid + (g >> 5) * NSM;
            const int rb = t >> 5, cb = t & 31;
            const int r0 = rb * 128 + wr * 32 + (lane >> 2);
            const int c0 = cb * 128 + wc * 32 + (lane & 3) * 2;
            #pragma unroll
            for (int mi = 0; mi < 2; mi++)
                #pragma unroll
                for (int ni = 0; ni < 4; ni++) {
                    const int rr = r0 + mi * 16;
                    const int cc = c0 + ni * 8;
                    float v[4];
                    #pragma unroll
                    for (int q = 0; q < 4; q++) {
                        float d = accD[mi][ni][q], p = accP[mi][ni][q];
                        v[q] = (p == 0.f) ? __int_as_float(0x7fc00000)
                                          : sqrtf(fmaxf(d, 0.f) * 1024.f / fmaxf(p, 1.f));
                        accD[mi][ni][q] = 0.f;
                        accP[mi][ni][q] = 0.f;
                    }
                    *reinterpret_cast<float2*>(out + (size_t)rr * 4096u + cc)       = make_float2(v[0], v[1]);
                    *reinterpret_cast<float2*>(out + (size_t)(rr + 8) * 4096u + cc) = make_float2(v[2], v[3]);
                }
        }
    }
}

// ---------------- launch ----------------
extern "C" void kernel_launch(void* const* d_in, const int* in_sizes, int n_in,
                              void* d_out, int out_size) {
    (void)in_sizes; (void)n_in; (void)out_size;
    const float* X = (const float*)d_in[0];
    const float* Y = (const float*)d_in[1];
    float* out = (float*)d_out;

    nanEuc_prep<<<4096, 256>>>(X, Y);

    cudaFuncSetAttribute(nanEuc_gemm, cudaFuncAttributeMaxDynamicSharedMemorySize, GSMEM);
    nanEuc_gemm<<<NSM, 512, GSMEM>>>(out);
}

// round 14
// speedup vs baseline: 1.9909x; 1.6641x over previous
#include <cuda_runtime.h>
#include <cuda_bf16.h>
#include <cstdint>
#include <cstring>

// NanEuclidean: X[4096,1024] f32, Y[4096,1024] f32 (10% NaN) -> out[4096,4096] f32
//   d = sqrt( clip(XX.pY - 2 Xc.Yc + pX.YY, 0) / max(1, pX.pY) * 1024 ), NaN where pc==0
//
// R14: two independent 256-thread CTAs per SM (CTA tile 128x64, warp tile 32x32
//      unchanged), 3-stage K32 pipeline, 36KB stages. Two barrier domains per SM
//      hide each other's sync/load latency. Prep identical to R11.

#define NKB    32            // K chunks of 32 per tile
#define TILE8K 8192u         // one 128-row x 64-byte swizzled tile image (A / B-pair)
#define STAGEB 36864u        // 3 A-planes (8K) + 3 B-planes (4K) = 36 KB
#define NSTAGE 3
#define GSMEM  (NSTAGE * STAGEB + 1024u)

// 24 MB each: [row_block(32)][comp(3)][k_block(32)] 8KB tiles
__device__ __align__(1024) __nv_bfloat16 g_nanEuc_A[12582912ull];
__device__ __align__(1024) __nv_bfloat16 g_nanEuc_B[12582912ull];

// ---------------- helpers ----------------
__device__ __forceinline__ uint32_t bf2_u32(__nv_bfloat162 v) {
    uint32_t u; memcpy(&u, &v, 4); return u;
}
__device__ __forceinline__ uint32_t smem_u32(const void* p) {
    uint32_t a;
    asm("{ .reg .u64 t; cvta.to.shared.u64 t, %1; cvt.u32.u64 %0, t; }" : "=r"(a) : "l"(p));
    return a;
}
__device__ __forceinline__ void cpasync16(uint32_t dst, const void* src) {
    asm volatile("cp.async.cg.shared.global [%0], [%1], 16;" :: "r"(dst), "l"(src) : "memory");
}
#define LDSM4(r0, r1, r2, r3, addr) \
    asm volatile("ldmatrix.sync.aligned.m8n8.x4.shared.b16 {%0,%1,%2,%3}, [%4];" \
        : "=r"(r0), "=r"(r1), "=r"(r2), "=r"(r3) : "r"(addr))

__device__ __forceinline__ void mma16816(float* c, const uint32_t* a, const uint32_t* b) {
    asm volatile(
        "mma.sync.aligned.m16n8k16.row.col.f32.bf16.bf16.f32 "
        "{%0,%1,%2,%3}, {%4,%5,%6,%7}, {%8,%9}, {%0,%1,%2,%3};"
        : "+f"(c[0]), "+f"(c[1]), "+f"(c[2]), "+f"(c[3])
        : "r"(a[0]), "r"(a[1]), "r"(a[2]), "r"(a[3]), "r"(b[0]), "r"(b[1]));
}
__device__ __forceinline__ bool nan_bits(float x) {
    return (__float_as_uint(x) & 0x7fffffffu) > 0x7f800000u;  // fast-math safe
}

// ---------------- Kernel 1: precompute swizzled bf16 component tiles ----------------
// A comps (from X): [XX, Xc, pX].  B comps (from Y): [pY, -2*Yc, YY].
// Tile: 128 rows x 64B (32 bf16). 16B seg s stored at local seg s ^ ((r>>1)&3).
__global__ void __launch_bounds__(256) nanEuc_prep(const float* __restrict__ X,
                                                   const float* __restrict__ Y) {
    const int is_b   = (int)(blockIdx.x >> 11);       // 2048 blocks per matrix
    const float* src = is_b ? Y : X;
    unsigned idx = (blockIdx.x & 2047u) * 256u + threadIdx.x;  // 0..524287
    unsigned s   = idx & 3u;              // 16B seg within 64B (8 bf16 = 8 f32 in)
    unsigned kb  = (idx >> 2) & 31u;      // k block of 32
    unsigned row = idx >> 7;              // 0..4095

    const float4 v0 = *reinterpret_cast<const float4*>(src + (size_t)row * 1024u + kb * 32u + s * 8u);
    const float4 v1 = *reinterpret_cast<const float4*>(src + (size_t)row * 1024u + kb * 32u + s * 8u + 4u);
    float x[8] = {v0.x, v0.y, v0.z, v0.w, v1.x, v1.y, v1.z, v1.w};

    uint32_t c0[4], c1[4], c2[4];         // 4 bf16x2 per comp
    #pragma unroll
    for (int i = 0; i < 4; i++) {
        float e0 = x[2 * i], e1 = x[2 * i + 1];
        bool  m0 = nan_bits(e0), m1 = nan_bits(e1);
        float a0 = m0 ? 0.f : e0, a1 = m1 ? 0.f : e1;
        float p0 = m0 ? 0.f : 1.f, p1 = m1 ? 0.f : 1.f;
        float q0 = a0 * a0, q1 = a1 * a1;
        if (!is_b) {
            c0[i] = bf2_u32(__floats2bfloat162_rn(q0, q1));                 // XX
            c1[i] = bf2_u32(__floats2bfloat162_rn(a0, a1));                 // Xc
            c2[i] = bf2_u32(__floats2bfloat162_rn(p0, p1));                 // pX
        } else {
            c0[i] = bf2_u32(__floats2bfloat162_rn(p0, p1));                 // pY
            c1[i] = bf2_u32(__floats2bfloat162_rn(-2.f * a0, -2.f * a1));   // -2Yc
            c2[i] = bf2_u32(__floats2bfloat162_rn(q0, q1));                 // YY
        }
    }

    unsigned rb = row >> 7, r = row & 127u;
    unsigned off = r * 64u + ((s ^ ((r >> 1) & 3u)) << 4);   // swizzled 16B slot
    char* dst = reinterpret_cast<char*>(is_b ? g_nanEuc_B : g_nanEuc_A);
    size_t tb = ((size_t)rb * 96u + kb) * 8192u;             // [rb][comp][kb]; comp stride 32*8192
    *reinterpret_cast<uint4*>(dst + tb +           off) = make_uint4(c0[0], c0[1], c0[2], c0[3]);
    *reinterpret_cast<uint4*>(dst + tb + 262144u + off) = make_uint4(c1[0], c1[1], c1[2], c1[3]);
    *reinterpret_cast<uint4*>(dst + tb + 524288u + off) = make_uint4(c2[0], c2[1], c2[2], c2[3]);
}

// ---------------- Kernel 2: mma.sync GEMM, 2 CTAs/SM ----------------
// 256 threads = 8 warps in 4x2; warp tile 32x32; CTA tile 128x64.
__global__ void __launch_bounds__(256, 2) nanEuc_gemm(float* __restrict__ out) {
    extern __shared__ char smraw[];
    const uint32_t smbase = (smem_u32(smraw) + 1023u) & ~1023u;

    const int tid = threadIdx.x, lane = tid & 31, w = tid >> 5;
    const int wr = w >> 1, wc = w & 1;            // 4 x 2 warp grid
    const int cb = blockIdx.x, rb = blockIdx.y;   // cb in 0..63 (64-wide tiles)

    const char* Ag = reinterpret_cast<const char*>(g_nanEuc_A);
    const char* Bg = reinterpret_cast<const char*>(g_nanEuc_B);

    float accD[2][4][4];
    float accP[2][4][4];
    #pragma unroll
    for (int mi = 0; mi < 2; mi++)
        #pragma unroll
        for (int ni = 0; ni < 4; ni++)
            #pragma unroll
            for (int q = 0; q < 4; q++) { accD[mi][ni][q] = 0.f; accP[mi][ni][q] = 0.f; }

    // ldmatrix lane addressing (64B rows, seg swizzle s^((row>>1)&3))
    const uint32_t hiA = (uint32_t)(lane >> 4);
    const uint32_t hiB = (uint32_t)((lane >> 3) & 1);
    uint32_t rtermA[2], xorA[2], rtermB[2], xorB[2];
    #pragma unroll
    for (int mi = 0; mi < 2; mi++) {
        uint32_t rowA = wr * 32 + mi * 16 + (lane & 15);
        rtermA[mi] = rowA * 64u;  xorA[mi] = (rowA >> 1) & 3u;
    }
    #pragma unroll
    for (int nt = 0; nt < 2; nt++) {
        uint32_t rowB = wc * 32 + nt * 16 + (lane & 7) + ((lane >> 4) & 1) * 8;  // 0..63 local
        rtermB[nt] = rowB * 64u;  xorB[nt] = (rowB >> 1) & 3u;
    }

    // stage loader: [A0 8K][A1 8K][A2 8K][B0 4K][B1 4K][B2 4K]; B = 64-row half-tile
    const uint32_t bhalf = (uint32_t)(cb & 1) * 4096u;
    auto load_stage = [&](int slot, int c) {
        const uint32_t dst0 = smbase + (uint32_t)slot * STAGEB;
        #pragma unroll
        for (int i = tid; i < (int)(STAGEB / 16u); i += 256) {
            const char* src;
            if (i < 1536) {
                int comp = i >> 9;
                src = Ag + ((size_t)(rb * 3 + comp) * NKB + c) * TILE8K + (size_t)(i & 511) * 16u;
            } else {
                int j = i - 1536;
                int comp = j >> 8;
                src = Bg + ((size_t)((cb >> 1) * 3 + comp) * NKB + c) * TILE8K
                    + bhalf + (size_t)(j & 255) * 16u;
            }
            cpasync16(dst0 + (uint32_t)i * 16u, src);
        }
    };

    // prologue: 2 stages in flight
    #pragma unroll
    for (int c = 0; c < NSTAGE - 1; c++) {
        load_stage(c, c);
        asm volatile("cp.async.commit_group;" ::: "memory");
    }

    int slot = 0;
    for (int c = 0; c < NKB; c++) {
        asm volatile("cp.async.wait_group %0;" :: "n"(NSTAGE - 2) : "memory");
        __syncthreads();
        if (c + NSTAGE - 1 < NKB) {
            int ns = slot + NSTAGE - 1; if (ns >= NSTAGE) ns -= NSTAGE;
            load_stage(ns, c + NSTAGE - 1);
        }
        asm volatile("cp.async.commit_group;" ::: "memory");   // empty group keeps count

        const uint32_t base = smbase + (uint32_t)slot * STAGEB;
        if (++slot == NSTAGE) slot = 0;

        #pragma unroll
        for (int kk = 0; kk < 2; kk++) {
            const uint32_t sA = (uint32_t)kk * 2u + hiA;
            const uint32_t sB = (uint32_t)kk * 2u + hiB;
            uint32_t a[2][4], b[4][2], bP[4][2];

            // ---- comp 0: D += XX . pY^T ; save pY frags for PC ----
            #pragma unroll
            for (int mi = 0; mi < 2; mi++)
                LDSM4(a[mi][0], a[mi][1], a[mi][2], a[mi][3],
                      base + 0u * 8192u + rtermA[mi] + ((sA ^ xorA[mi]) << 4));
            #pragma unroll
            for (int nt = 0; nt < 2; nt++)
                LDSM4(b[2 * nt][0], b[2 * nt][1], b[2 * nt + 1][0], b[2 * nt + 1][1],
                      base + 24576u + 0u * 4096u + rtermB[nt] + ((sB ^ xorB[nt]) << 4));
            #pragma unroll
            for (int ni = 0; ni < 4; ni++) { bP[ni][0] = b[ni][0]; bP[ni][1] = b[ni][1]; }
            #pragma unroll
            for (int mi = 0; mi < 2; mi++)
                #pragma unroll
                for (int ni = 0; ni < 4; ni++) mma16816(accD[mi][ni], a[mi], b[ni]);

            // ---- comp 1: D += Xc . (-2 Yc)^T ----
            #pragma unroll
            for (int mi = 0; mi < 2; mi++)
                LDSM4(a[mi][0], a[mi][1], a[mi][2], a[mi][3],
                      base + 1u * 8192u + rtermA[mi] + ((sA ^ xorA[mi]) << 4));
            #pragma unroll
            for (int nt = 0; nt < 2; nt++)
                LDSM4(b[2 * nt][0], b[2 * nt][1], b[2 * nt + 1][0], b[2 * nt + 1][1],
                      base + 24576u + 1u * 4096u + rtermB[nt] + ((sB ^ xorB[nt]) << 4));
            #pragma unroll
            for (int mi = 0; mi < 2; mi++)
                #pragma unroll
                for (int ni = 0; ni < 4; ni++) mma16816(accD[mi][ni], a[mi], b[ni]);

            // ---- comp 2: D += pX . YY^T ; PC += pX . pY^T (reuses bP) ----
            #pragma unroll
            for (int mi = 0; mi < 2; mi++)
                LDSM4(a[mi][0], a[mi][1], a[mi][2], a[mi][3],
                      base + 2u * 8192u + rtermA[mi] + ((sA ^ xorA[mi]) << 4));
            #pragma unroll
            for (int nt = 0; nt < 2; nt++)
                LDSM4(b[2 * nt][0], b[2 * nt][1], b[2 * nt + 1][0], b[2 * nt + 1][1],
                      base + 24576u + 2u * 4096u + rtermB[nt] + ((sB ^ xorB[nt]) << 4));
            #pragma unroll
            for (int mi = 0; mi < 2; mi++)
                #pragma unroll
                for (int ni = 0; ni < 4; ni++) {
                    mma16816(accD[mi][ni], a[mi], b[ni]);
                    mma16816(accP[mi][ni], a[mi], bP[ni]);
                }
        }
    }

    // ---- epilogue: r = pc==0 ? NaN : sqrt(max(d,0) * 1024 / max(pc,1)) ----
    const int r0 = rb * 128 + wr * 32 + (lane >> 2);
    const int c0 = cb * 64 + wc * 32 + (lane & 3) * 2;
    #pragma unroll
    for (int mi = 0; mi < 2; mi++)
        #pragma unroll
        for (int ni = 0; ni < 4; ni++) {
            const int rr = r0 + mi * 16;
            const int cc = c0 + ni * 8;
            float v[4];
            #pragma unroll
            for (int q = 0; q < 4; q++) {
                float d = accD[mi][ni][q], p = accP[mi][ni][q];
                v[q] = (p == 0.f) ? __int_as_float(0x7fc00000)
                                  : sqrtf(fmaxf(d, 0.f) * 1024.f / fmaxf(p, 1.f));
            }
            *reinterpret_cast<float2*>(out + (size_t)rr * 4096u + cc)       = make_float2(v[0], v[1]);
            *reinterpret_cast<float2*>(out + (size_t)(rr + 8) * 4096u + cc) = make_float2(v[2], v[3]);
        }
}

// ---------------- launch ----------------
extern "C" void kernel_launch(void* const* d_in, const int* in_sizes, int n_in,
                              void* d_out, int out_size) {
    (void)in_sizes; (void)n_in; (void)out_size;
    const float* X = (const float*)d_in[0];
    const float* Y = (const float*)d_in[1];
    float* out = (float*)d_out;

    nanEuc_prep<<<4096, 256>>>(X, Y);

    cudaFuncSetAttribute(nanEuc_gemm, cudaFuncAttributeMaxDynamicSharedMemorySize, GSMEM);
    nanEuc_gemm<<<dim3(64, 32, 1), 256, GSMEM>>>(out);
}

// round 15
// speedup vs baseline: 2.1197x; 1.0647x over previous
#include <cuda_runtime.h>
#include <cuda_bf16.h>
#include <cstdint>
#include <cstring>

// NanEuclidean: X[4096,1024] f32, Y[4096,1024] f32 (10% NaN) -> out[4096,4096] f32
//   d = sqrt( clip(XX.pY - 2 Xc.Yc + pX.YY, 0) / max(1, pX.pY) * 1024 ), NaN where pc==0
//
// R15 = R14 (2 CTAs/SM, 128x64 tile, 32x32 warp tile) + register-derived squared
//       planes: store only [-2Xc,pX] / [Yc,pY]; XX,YY fragments computed in-register
//       via mul.rn.bf16x2. Stage 24KB, 4-stage pipeline, -33% LDSM, -35% cp.async.

#define NKB    32            // K chunks of 32 per tile
#define TILE8K 8192u         // one 128-row x 64-byte swizzled tile image
#define STAGEB 24576u        // A planes 2x8K + B half-planes 2x4K
#define NSTAGE 4
#define GSMEM  (NSTAGE * STAGEB + 1024u)

// 16 MB each: [row_block(32)][comp(2)][k_block(32)] 8KB tiles
__device__ __align__(1024) __nv_bfloat16 g_nanEuc_A[8388608ull];
__device__ __align__(1024) __nv_bfloat16 g_nanEuc_B[8388608ull];

// ---------------- helpers ----------------
__device__ __forceinline__ uint32_t bf2_u32(__nv_bfloat162 v) {
    uint32_t u; memcpy(&u, &v, 4); return u;
}
__device__ __forceinline__ uint32_t smem_u32(const void* p) {
    uint32_t a;
    asm("{ .reg .u64 t; cvta.to.shared.u64 t, %1; cvt.u32.u64 %0, t; }" : "=r"(a) : "l"(p));
    return a;
}
__device__ __forceinline__ void cpasync16(uint32_t dst, const void* src) {
    asm volatile("cp.async.cg.shared.global [%0], [%1], 16;" :: "r"(dst), "l"(src) : "memory");
}
__device__ __forceinline__ uint32_t bmul2(uint32_t a, uint32_t b) {
    uint32_t d;
    asm("mul.rn.bf16x2 %0, %1, %2;" : "=r"(d) : "r"(a), "r"(b));
    return d;
}
#define LDSM4(r0, r1, r2, r3, addr) \
    asm volatile("ldmatrix.sync.aligned.m8n8.x4.shared.b16 {%0,%1,%2,%3}, [%4];" \
        : "=r"(r0), "=r"(r1), "=r"(r2), "=r"(r3) : "r"(addr))

__device__ __forceinline__ void mma16816(float* c, const uint32_t* a, const uint32_t* b) {
    asm volatile(
        "mma.sync.aligned.m16n8k16.row.col.f32.bf16.bf16.f32 "
        "{%0,%1,%2,%3}, {%4,%5,%6,%7}, {%8,%9}, {%0,%1,%2,%3};"
        : "+f"(c[0]), "+f"(c[1]), "+f"(c[2]), "+f"(c[3])
        : "r"(a[0]), "r"(a[1]), "r"(a[2]), "r"(a[3]), "r"(b[0]), "r"(b[1]));
}
__device__ __forceinline__ bool nan_bits(float x) {
    return (__float_as_uint(x) & 0x7fffffffu) > 0x7f800000u;  // fast-math safe
}

// ---------------- Kernel 1: precompute swizzled bf16 component tiles ----------------
// A comps (from X): [-2Xc, pX].  B comps (from Y): [Yc, pY].
// Tile: 128 rows x 64B (32 bf16). 16B seg s stored at local seg s ^ ((r>>1)&3).
__global__ void __launch_bounds__(256) nanEuc_prep(const float* __restrict__ X,
                                                   const float* __restrict__ Y) {
    const int is_b   = (int)(blockIdx.x >> 11);       // 2048 blocks per matrix
    const float* src = is_b ? Y : X;
    unsigned idx = (blockIdx.x & 2047u) * 256u + threadIdx.x;  // 0..524287
    unsigned s   = idx & 3u;              // 16B seg within 64B
    unsigned kb  = (idx >> 2) & 31u;      // k block of 32
    unsigned row = idx >> 7;              // 0..4095

    const float4 v0 = *reinterpret_cast<const float4*>(src + (size_t)row * 1024u + kb * 32u + s * 8u);
    const float4 v1 = *reinterpret_cast<const float4*>(src + (size_t)row * 1024u + kb * 32u + s * 8u + 4u);
    float x[8] = {v0.x, v0.y, v0.z, v0.w, v1.x, v1.y, v1.z, v1.w};

    uint32_t c0[4], c1[4];                // 4 bf16x2 per comp
    #pragma unroll
    for (int i = 0; i < 4; i++) {
        float e0 = x[2 * i], e1 = x[2 * i + 1];
        bool  m0 = nan_bits(e0), m1 = nan_bits(e1);
        float a0 = m0 ? 0.f : e0, a1 = m1 ? 0.f : e1;
        float p0 = m0 ? 0.f : 1.f, p1 = m1 ? 0.f : 1.f;
        float f0 = is_b ? a0 : -2.f * a0;
        float f1 = is_b ? a1 : -2.f * a1;
        c0[i] = bf2_u32(__floats2bfloat162_rn(f0, f1));   // A: -2Xc   B: Yc
        c1[i] = bf2_u32(__floats2bfloat162_rn(p0, p1));   // presence
    }

    unsigned rb = row >> 7, r = row & 127u;
    unsigned off = r * 64u + ((s ^ ((r >> 1) & 3u)) << 4);   // swizzled 16B slot
    char* dst = reinterpret_cast<char*>(is_b ? g_nanEuc_B : g_nanEuc_A);
    size_t tb = ((size_t)rb * 64u + kb) * 8192u;             // [rb][comp][kb]; comp stride 32*8192
    *reinterpret_cast<uint4*>(dst + tb +           off) = make_uint4(c0[0], c0[1], c0[2], c0[3]);
    *reinterpret_cast<uint4*>(dst + tb + 262144u + off) = make_uint4(c1[0], c1[1], c1[2], c1[3]);
}

// ---------------- Kernel 2: mma.sync GEMM, 2 CTAs/SM, derived squares ----------------
// 256 threads = 8 warps in 4x2; warp tile 32x32; CTA tile 128x64.
__global__ void __launch_bounds__(256, 2) nanEuc_gemm(float* __restrict__ out) {
    extern __shared__ char smraw[];
    const uint32_t smbase = (smem_u32(smraw) + 1023u) & ~1023u;

    const int tid = threadIdx.x, lane = tid & 31, w = tid >> 5;
    const int wr = w >> 1, wc = w & 1;            // 4 x 2 warp grid
    const int cb = blockIdx.x, rb = blockIdx.y;   // cb in 0..63 (64-wide tiles)

    const char* Ag = reinterpret_cast<const char*>(g_nanEuc_A);
    const char* Bg = reinterpret_cast<const char*>(g_nanEuc_B);
    const uint32_t QUARTER2 = 0x3E803E80u;        // bf16x2 {0.25, 0.25}

    float accD[2][4][4];
    float accP[2][4][4];
    #pragma unroll
    for (int mi = 0; mi < 2; mi++)
        #pragma unroll
        for (int ni = 0; ni < 4; ni++)
            #pragma unroll
            for (int q = 0; q < 4; q++) { accD[mi][ni][q] = 0.f; accP[mi][ni][q] = 0.f; }

    // ldmatrix lane addressing (64B rows, seg swizzle s^((row>>1)&3))
    const uint32_t hiA = (uint32_t)(lane >> 4);
    const uint32_t hiB = (uint32_t)((lane >> 3) & 1);
    uint32_t rtermA[2], xorA[2], rtermB[2], xorB[2];
    #pragma unroll
    for (int mi = 0; mi < 2; mi++) {
        uint32_t rowA = wr * 32 + mi * 16 + (lane & 15);
        rtermA[mi] = rowA * 64u;  xorA[mi] = (rowA >> 1) & 3u;
    }
    #pragma unroll
    for (int nt = 0; nt < 2; nt++) {
        uint32_t rowB = wc * 32 + nt * 16 + (lane & 7) + ((lane >> 4) & 1) * 8;  // local 0..63
        rtermB[nt] = rowB * 64u;  xorB[nt] = (rowB >> 1) & 3u;
    }

    // stage layout: [A s-plane 8K][A pX 8K][B Yc-half 4K][B pY-half 4K]
    const uint32_t bhalf = (uint32_t)(cb & 1) * 4096u;
    auto load_stage = [&](int slot, int c) {
        const uint32_t dst0 = smbase + (uint32_t)slot * STAGEB;
        #pragma unroll
        for (int i = tid; i < (int)(STAGEB / 16u); i += 256) {
            const char* src;
            if (i < 1024) {
                int comp = i >> 9;
                src = Ag + ((size_t)(rb * 2 + comp) * NKB + c) * TILE8K + (size_t)(i & 511) * 16u;
            } else {
                int j = i - 1024;
                int comp = j >> 8;
                src = Bg + ((size_t)((cb >> 1) * 2 + comp) * NKB + c) * TILE8K
                    + bhalf + (size_t)(j & 255) * 16u;
            }
            cpasync16(dst0 + (uint32_t)i * 16u, src);
        }
    };

    // prologue: 3 stages in flight
    #pragma unroll
    for (int c = 0; c < NSTAGE - 1; c++) {
        load_stage(c, c);
        asm volatile("cp.async.commit_group;" ::: "memory");
    }

    int slot = 0;
    for (int c = 0; c < NKB; c++) {
        asm volatile("cp.async.wait_group %0;" :: "n"(NSTAGE - 2) : "memory");
        __syncthreads();
        if (c + NSTAGE - 1 < NKB) {
            int ns = slot + NSTAGE - 1; if (ns >= NSTAGE) ns -= NSTAGE;
            load_stage(ns, c + NSTAGE - 1);
        }
        asm volatile("cp.async.commit_group;" ::: "memory");   // empty group keeps count

        const uint32_t base = smbase + (uint32_t)slot * STAGEB;
        if (++slot == NSTAGE) slot = 0;

        #pragma unroll
        for (int kk = 0; kk < 2; kk++) {
            const uint32_t sA = (uint32_t)kk * 2u + hiA;
            const uint32_t sB = (uint32_t)kk * 2u + hiB;
            uint32_t a[2][4], b1[4][2], b2[4][2];

            // ---- comp 1: D += (-2Xc) . Yc^T ----
            #pragma unroll
            for (int mi = 0; mi < 2; mi++)
                LDSM4(a[mi][0], a[mi][1], a[mi][2], a[mi][3],
                      base + 0u * 8192u + rtermA[mi] + ((sA ^ xorA[mi]) << 4));
            #pragma unroll
            for (int nt = 0; nt < 2; nt++)
                LDSM4(b1[2 * nt][0], b1[2 * nt][1], b1[2 * nt + 1][0], b1[2 * nt + 1][1],
                      base + 16384u + rtermB[nt] + ((sB ^ xorB[nt]) << 4));
            #pragma unroll
            for (int mi = 0; mi < 2; mi++)
                #pragma unroll
                for (int ni = 0; ni < 4; ni++) mma16816(accD[mi][ni], a[mi], b1[ni]);

            // ---- comp 0: D += XX . pY^T  (XX = (-2Xc)^2 * 0.25, in-register) ----
            #pragma unroll
            for (int nt = 0; nt < 2; nt++)
                LDSM4(b2[2 * nt][0], b2[2 * nt][1], b2[2 * nt + 1][0], b2[2 * nt + 1][1],
                      base + 20480u + rtermB[nt] + ((sB ^ xorB[nt]) << 4));
            #pragma unroll
            for (int mi = 0; mi < 2; mi++)
                #pragma unroll
                for (int r4 = 0; r4 < 4; r4++)
                    a[mi][r4] = bmul2(bmul2(a[mi][r4], a[mi][r4]), QUARTER2);
            #pragma unroll
            for (int mi = 0; mi < 2; mi++)
                #pragma unroll
                for (int ni = 0; ni < 4; ni++) mma16816(accD[mi][ni], a[mi], b2[ni]);

            // ---- comp 2: D += pX . YY^T (YY = Yc^2 in-register); PC += pX . pY^T ----
            #pragma unroll
            for (int mi = 0; mi < 2; mi++)
                LDSM4(a[mi][0], a[mi][1], a[mi][2], a[mi][3],
                      base + 8192u + rtermA[mi] + ((sA ^ xorA[mi]) << 4));
            #pragma unroll
            for (int ni = 0; ni < 4; ni++) {
                b1[ni][0] = bmul2(b1[ni][0], b1[ni][0]);
                b1[ni][1] = bmul2(b1[ni][1], b1[ni][1]);
            }
            #pragma unroll
            for (int mi = 0; mi < 2; mi++)
                #pragma unroll
                for (int ni = 0; ni < 4; ni++) {
                    mma16816(accD[mi][ni], a[mi], b1[ni]);
                    mma16816(accP[mi][ni], a[mi], b2[ni]);
                }
        }
    }

    // ---- epilogue: r = pc==0 ? NaN : sqrt(max(d,0) * 1024 / max(pc,1)) ----
    const int r0 = rb * 128 + wr * 32 + (lane >> 2);
    const int c0 = cb * 64 + wc * 32 + (lane & 3) * 2;
    #pragma unroll
    for (int mi = 0; mi < 2; mi++)
        #pragma unroll
        for (int ni = 0; ni < 4; ni++) {
            const int rr = r0 + mi * 16;
            const int cc = c0 + ni * 8;
            float v[4];
            #pragma unroll
            for (int q = 0; q < 4; q++) {
                float d = accD[mi][ni][q], p = accP[mi][ni][q];
                v[q] = (p == 0.f) ? __int_as_float(0x7fc00000)
                                  : sqrtf(fmaxf(d, 0.f) * 1024.f / fmaxf(p, 1.f));
            }
            *reinterpret_cast<float2*>(out + (size_t)rr * 4096u + cc)       = make_float2(v[0], v[1]);
            *reinterpret_cast<float2*>(out + (size_t)(rr + 8) * 4096u + cc) = make_float2(v[2], v[3]);
        }
}

// ---------------- launch ----------------
extern "C" void kernel_launch(void* const* d_in, const int* in_sizes, int n_in,
                              void* d_out, int out_size) {
    (void)in_sizes; (void)n_in; (void)out_size;
    const float* X = (const float*)d_in[0];
    const float* Y = (const float*)d_in[1];
    float* out = (float*)d_out;

    nanEuc_prep<<<4096, 256>>>(X, Y);

    cudaFuncSetAttribute(nanEuc_gemm, cudaFuncAttributeMaxDynamicSharedMemorySize, GSMEM);
    nanEuc_gemm<<<dim3(64, 32, 1), 256, GSMEM>>>(out);
}